// round 4
// baseline (speedup 1.0000x reference)
#include <cuda_runtime.h>
#include <cuda_fp16.h>
#include <cstdint>

// ---------------------------------------------------------------------------
// voltageNN: 2-layer LSTM (H=256, proj P=1, in=1, T=1000) + MLP head, B=16384.
// Hybrid precision: gate pre-activations + h + reductions in f32 (FMA pipe has
// headroom), tanh via tanh.approx.f16x2 (halves the MUFU bottleneck), post-tanh
// cell math in half2. Only 2 scalar H2F converts per step.
// ---------------------------------------------------------------------------

#define HID   256
#define TLEN  1000
#define FULLM 0xffffffffu

// f32 gate weights, gate order: 0=i, 1=f, 2=o, 3=g. i/f/o pre-scaled by 0.5
// (sigmoid(x) = 0.5*tanh(0.5x)+0.5). Indexed [layer][gate][unit].
__device__ float   g_wx[2][4][HID];
__device__ float   g_wh[2][4][HID];
__device__ float   g_wb[2][4][HID];
// Projection Whr packed half2: [layer][pair 0..3][lane]; lo=unit lane+64p, hi=+32.
__device__ __half2 h_wr[2][4][32];
__device__ float   g_w1t[TLEN * 128];    // W1 transposed + padded: [t][j]
__device__ float   g_b1p[128];
__device__ float   g_w2p[128];

__device__ __forceinline__ __half2 tanh2(__half2 v) {
    uint32_t a = *reinterpret_cast<uint32_t*>(&v);
    uint32_t r;
    asm("tanh.approx.f16x2 %0, %1;" : "=r"(r) : "r"(a));
    return *reinterpret_cast<__half2*>(&r);
}

// ---------------------------------------------------------------------------
// Prep kernel: pack/transpose weights. grid = TLEN+1 blocks x 128 threads.
// ---------------------------------------------------------------------------
__global__ void prep_kernel(
    const float* __restrict__ Wih0, const float* __restrict__ Whh0,
    const float* __restrict__ bih0, const float* __restrict__ bhh0,
    const float* __restrict__ Whr0,
    const float* __restrict__ Wih1, const float* __restrict__ Whh1,
    const float* __restrict__ bih1, const float* __restrict__ bhh1,
    const float* __restrict__ Whr1,
    const float* __restrict__ W1,  const float* __restrict__ b1,
    const float* __restrict__ W2)
{
    int tid = threadIdx.x;
    int blk = blockIdx.x;
    if (blk < TLEN) {
        int t = blk;
        int j = tid;  // 0..127
        g_w1t[t * 128 + j] = (j < 100) ? W1[j * TLEN + t] : 0.0f;
        return;
    }
    // blk == TLEN: pack LSTM weights + head vectors
    for (int i = tid; i < 2 * HID; i += 128) {
        int layer = i >> 8;
        int k = i & (HID - 1);
        const float* Wih = layer ? Wih1 : Wih0;
        const float* Whh = layer ? Whh1 : Whh0;
        const float* bih = layer ? bih1 : bih0;
        const float* bhh = layer ? bhh1 : bhh0;
        // source gate stacking: i [0,256), f [256,512), g [512,768), o [768,1024)
        const int rows[4] = {0, 256, 768, 512};   // our order: i, f, o, g
        const float scl[4] = {0.5f, 0.5f, 0.5f, 1.0f};
#pragma unroll
        for (int gte = 0; gte < 4; gte++) {
            int r = rows[gte];
            float s = scl[gte];
            g_wx[layer][gte][k] = s * Wih[r + k];
            g_wh[layer][gte][k] = s * Whh[r + k];
            g_wb[layer][gte][k] = s * (bih[r + k] + bhh[r + k]);
        }
    }
    // Whr half2 packing: 2 layers x 4 pairs x 32 lanes
    for (int i = tid; i < 256; i += 128) {
        int layer = i >> 7;
        int rem   = i & 127;
        int p     = rem >> 5;
        int lane  = rem & 31;
        int klo = lane + 64 * p;
        const float* Whr = layer ? Whr1 : Whr0;
        h_wr[layer][p][lane] = __floats2half2_rn(Whr[klo], Whr[klo + 32]);
    }
    if (tid < 128) {
        g_b1p[tid] = (tid < 100) ? b1[tid] : 0.0f;
        g_w2p[tid] = (tid < 100) ? W2[tid] : 0.0f;
    }
}

// ---------------------------------------------------------------------------
// One LSTM step. 8 units/lane as 4 pairs. f32 pre-activations, f16x2 tanh,
// half2 cell math, f32 reduction. Returns projected scalar h (f32, all lanes).
// ---------------------------------------------------------------------------
__device__ __forceinline__ float lstm_step(
    float xv, float h,
    const float (*wxl)[4], const float (*wxh)[4],
    const float (*whl)[4], const float (*whh_)[4],
    const float (*wbl)[4], const float (*wbh)[4],
    const __half2* wr, __half2* c, __half2 halfc)
{
    __half2 part = __floats2half2_rn(0.0f, 0.0f);
#pragma unroll
    for (int p = 0; p < 4; p++) {
        float ail = fmaf(xv, wxl[p][0], fmaf(h, whl[p][0], wbl[p][0]));
        float aih = fmaf(xv, wxh[p][0], fmaf(h, whh_[p][0], wbh[p][0]));
        float afl = fmaf(xv, wxl[p][1], fmaf(h, whl[p][1], wbl[p][1]));
        float afh = fmaf(xv, wxh[p][1], fmaf(h, whh_[p][1], wbh[p][1]));
        float aol = fmaf(xv, wxl[p][2], fmaf(h, whl[p][2], wbl[p][2]));
        float aoh = fmaf(xv, wxh[p][2], fmaf(h, whh_[p][2], wbh[p][2]));
        float agl = fmaf(xv, wxl[p][3], fmaf(h, whl[p][3], wbl[p][3]));
        float agh = fmaf(xv, wxh[p][3], fmaf(h, whh_[p][3], wbh[p][3]));
        __half2 ti = tanh2(__floats2half2_rn(ail, aih));
        __half2 tf = tanh2(__floats2half2_rn(afl, afh));
        __half2 to = tanh2(__floats2half2_rn(aol, aoh));
        __half2 tg = tanh2(__floats2half2_rn(agl, agh));
        __half2 gi = __hfma2(ti, halfc, halfc);
        __half2 gf = __hfma2(tf, halfc, halfc);
        __half2 go = __hfma2(to, halfc, halfc);
        __half2 cm = __hfma2(gf, c[p], __hmul2(gi, tg));
        c[p] = cm;
        part = __hfma2(__hmul2(go, tanh2(cm)), wr[p], part);
    }
    // cross-lane + cross-half reduction in f32
    float ps = __half2float(__low2half(part)) + __half2float(__high2half(part));
#pragma unroll
    for (int s = 16; s; s >>= 1)
        ps += __shfl_xor_sync(FULLM, ps, s);
    return ps;
}

// ---------------------------------------------------------------------------
// Main kernel: 1 warp per batch element, 4 warps/block.
// ---------------------------------------------------------------------------
__global__ __launch_bounds__(128, 3) void lstm_kernel(
    const float* __restrict__ x,
    const float* __restrict__ b2,
    float* __restrict__ out)
{
    __shared__ float sbuf[4][TLEN + 8];

    int warp = threadIdx.x >> 5;
    int lane = threadIdx.x & 31;
    int b = blockIdx.x * 4 + warp;
    const float* xb = x + (size_t)b * TLEN;

    const __half2 halfc = __floats2half2_rn(0.5f, 0.5f);
    const __half2 zero2 = __floats2half2_rn(0.0f, 0.0f);

    float wxl[4][4], wxh[4][4], whl[4][4], whh_[4][4], wbl[4][4], wbh[4][4];
    __half2 wr[4], c[4];

    // ---------------- pass 1: layer 0 ----------------
#pragma unroll
    for (int p = 0; p < 4; p++) {
        int klo = lane + 64 * p;
#pragma unroll
        for (int gte = 0; gte < 4; gte++) {
            wxl[p][gte]  = g_wx[0][gte][klo];
            wxh[p][gte]  = g_wx[0][gte][klo + 32];
            whl[p][gte]  = g_wh[0][gte][klo];
            whh_[p][gte] = g_wh[0][gte][klo + 32];
            wbl[p][gte]  = g_wb[0][gte][klo];
            wbh[p][gte]  = g_wb[0][gte][klo + 32];
        }
        wr[p] = h_wr[0][p][lane];
        c[p] = zero2;
    }
    float h = 0.0f;
    float xr = 0.0f;
    for (int t = 0; t < TLEN; t++) {
        if ((t & 31) == 0) {
            int ti = t + lane;
            xr = xb[(ti < TLEN) ? ti : (TLEN - 1)];
        }
        float xv = __shfl_sync(FULLM, xr, t & 31);
        h = lstm_step(xv, h, wxl, wxh, whl, whh_, wbl, wbh, wr, c, halfc);
        if (lane == 0) sbuf[warp][t] = h;
    }
    __syncwarp();

    // ---------------- pass 2: layer 1 + fused head ----------------
#pragma unroll
    for (int p = 0; p < 4; p++) {
        int klo = lane + 64 * p;
#pragma unroll
        for (int gte = 0; gte < 4; gte++) {
            wxl[p][gte]  = g_wx[1][gte][klo];
            wxh[p][gte]  = g_wx[1][gte][klo + 32];
            whl[p][gte]  = g_wh[1][gte][klo];
            whh_[p][gte] = g_wh[1][gte][klo + 32];
            wbl[p][gte]  = g_wb[1][gte][klo];
            wbh[p][gte]  = g_wb[1][gte][klo + 32];
        }
        wr[p] = h_wr[1][p][lane];
        c[p] = zero2;
    }
    h = 0.0f;
    float a0 = 0.0f, a1 = 0.0f, a2 = 0.0f, a3 = 0.0f;
    for (int t = 0; t < TLEN; t++) {
        float xv = sbuf[warp][t];
        h = lstm_step(xv, h, wxl, wxh, whl, whh_, wbl, wbh, wr, c, halfc);
        const float* wrow = g_w1t + t * 128;
        a0 = fmaf(h, wrow[lane     ], a0);
        a1 = fmaf(h, wrow[lane + 32], a1);
        a2 = fmaf(h, wrow[lane + 64], a2);
        a3 = fmaf(h, wrow[lane + 96], a3);
    }

    // head: out = relu(acc + b1) @ W2 + b2   (padding is zero -> no effect)
    float s = fmaxf(a0 + g_b1p[lane     ], 0.0f) * g_w2p[lane     ]
            + fmaxf(a1 + g_b1p[lane + 32], 0.0f) * g_w2p[lane + 32]
            + fmaxf(a2 + g_b1p[lane + 64], 0.0f) * g_w2p[lane + 64]
            + fmaxf(a3 + g_b1p[lane + 96], 0.0f) * g_w2p[lane + 96];
#pragma unroll
    for (int sf = 16; sf; sf >>= 1)
        s += __shfl_xor_sync(FULLM, s, sf);
    if (lane == 0) out[b] = s + b2[0];
}

// ---------------------------------------------------------------------------
// kernel_launch
// ---------------------------------------------------------------------------
extern "C" void kernel_launch(void* const* d_in, const int* in_sizes, int n_in,
                              void* d_out, int out_size)
{
    const float* x    = (const float*)d_in[0];
    const float* Wih0 = (const float*)d_in[1];
    const float* Whh0 = (const float*)d_in[2];
    const float* bih0 = (const float*)d_in[3];
    const float* bhh0 = (const float*)d_in[4];
    const float* Whr0 = (const float*)d_in[5];
    const float* Wih1 = (const float*)d_in[6];
    const float* Whh1 = (const float*)d_in[7];
    const float* bih1 = (const float*)d_in[8];
    const float* bhh1 = (const float*)d_in[9];
    const float* Whr1 = (const float*)d_in[10];
    const float* W1   = (const float*)d_in[11];
    const float* b1   = (const float*)d_in[12];
    const float* W2   = (const float*)d_in[13];
    const float* b2   = (const float*)d_in[14];
    float* out = (float*)d_out;

    int B = in_sizes[0] / TLEN;   // 16384

    prep_kernel<<<TLEN + 1, 128>>>(Wih0, Whh0, bih0, bhh0, Whr0,
                                   Wih1, Whh1, bih1, bhh1, Whr1,
                                   W1, b1, W2);
    lstm_kernel<<<B / 4, 128>>>(x, b2, out);
}